// round 6
// baseline (speedup 1.0000x reference)
#include <cuda_runtime.h>

#define NTREES 128
#define C 8
#define L 2
#define M 256
#define G 4
#define NTH 1024

typedef unsigned long long u64;

// Precomputed (softmaxed) parameters. SP folded into A.
__device__ float g_A[C][C][L][G];   // [c][d][p][g]
__device__ float g_Bm[C][M][G];
__device__ float g_Pi[L][C][G];

// ---------------- packed f32x2 helpers ----------------
static __device__ __forceinline__ u64 pk2f(float lo, float hi) {
    u64 r; asm("mov.b64 %0,{%1,%2};" : "=l"(r) : "f"(lo), "f"(hi)); return r;
}
static __device__ __forceinline__ void unpk2f(u64 v, float& lo, float& hi) {
    asm("mov.b64 {%0,%1},%2;" : "=f"(lo), "=f"(hi) : "l"(v));
}
static __device__ __forceinline__ u64 fma2p(u64 a, u64 b, u64 c) {
    u64 d; asm("fma.rn.f32x2 %0,%1,%2,%3;" : "=l"(d) : "l"(a), "l"(b), "l"(c)); return d;
}
static __device__ __forceinline__ u64 mul2p(u64 a, u64 b) {
    u64 d; asm("mul.rn.f32x2 %0,%1,%2;" : "=l"(d) : "l"(a), "l"(b)); return d;
}
static __device__ __forceinline__ u64 add2p(u64 a, u64 b) {
    u64 d; asm("add.rn.f32x2 %0,%1,%2;" : "=l"(d) : "l"(a), "l"(b)); return d;
}

// 8x8 packed matvec using ulonglong2 A rows (LDS.128): out[c] (+)= sum_d A[c][d]*b[d]
static __device__ __forceinline__ void matvec8(const ulonglong2* __restrict__ A2,
                                               const u64* __restrict__ b,
                                               u64* __restrict__ outv, bool accumulate) {
#pragma unroll
    for (int c = 0; c < 8; c++) {
        u64 mm = accumulate ? outv[c] : 0ull;
#pragma unroll
        for (int d2 = 0; d2 < 4; d2++) {
            ulonglong2 a = A2[c * 4 + d2];
            mm = fma2p(a.x, b[2 * d2], mm);
            mm = fma2p(a.y, b[2 * d2 + 1], mm);
        }
        outv[c] = mm;
    }
}

// ---------------- precompute softmaxes (parallel) ----------------
__global__ void htmm_precompute(const float* __restrict__ lA, const float* __restrict__ lB,
                                const float* __restrict__ lPi, const float* __restrict__ lSP) {
    const int tid = threadIdx.x;
    const int wid = tid >> 5, lane = tid & 31;

    // Bm: one warp per (c,g)
    {
        int c = wid >> 2, g = wid & 3;
        float v[8];
        float mx = -1e30f;
#pragma unroll
        for (int j = 0; j < 8; j++) {
            int m = lane + 32 * j;
            v[j] = lB[(c * M + m) * G + g];
            mx = fmaxf(mx, v[j]);
        }
#pragma unroll
        for (int o = 16; o; o >>= 1) mx = fmaxf(mx, __shfl_xor_sync(0xffffffffu, mx, o));
        float s = 0.f;
#pragma unroll
        for (int j = 0; j < 8; j++) { v[j] = __expf(v[j] - mx); s += v[j]; }
#pragma unroll
        for (int o = 16; o; o >>= 1) s += __shfl_xor_sync(0xffffffffu, s, o);
        float r = 1.f / s;
#pragma unroll
        for (int j = 0; j < 8; j++) g_Bm[c][lane + 32 * j][g] = v[j] * r;
    }

    if (tid < 64) {
        int d = tid >> 3, p = (tid >> 2) & 1, g = tid & 3;
        float s0 = lSP[0 * G + g], s1 = lSP[1 * G + g];
        float mxs = fmaxf(s0, s1);
        float e0 = __expf(s0 - mxs), e1 = __expf(s1 - mxs);
        float sp = (p == 0 ? e0 : e1) / (e0 + e1);
        float mx = -1e30f;
#pragma unroll
        for (int c = 0; c < C; c++) mx = fmaxf(mx, lA[((c * C + d) * L + p) * G + g]);
        float s = 0.f;
#pragma unroll
        for (int c = 0; c < C; c++) s += __expf(lA[((c * C + d) * L + p) * G + g] - mx);
        float r = sp / s;
#pragma unroll
        for (int c = 0; c < C; c++)
            g_A[c][d][p][g] = __expf(lA[((c * C + d) * L + p) * G + g] - mx) * r;
    } else if (tid < 72) {
        int t2 = tid - 64;
        int p = t2 >> 2, g = t2 & 3;
        float mx = -1e30f;
#pragma unroll
        for (int c = 0; c < C; c++) mx = fmaxf(mx, lPi[(c * L + p) * G + g]);
        float s = 0.f;
#pragma unroll
        for (int c = 0; c < C; c++) s += __expf(lPi[(c * L + p) * G + g] - mx);
        float r = 1.f / s;
#pragma unroll
        for (int c = 0; c < C; c++) g_Pi[p][c][g] = __expf(lPi[(c * L + p) * G + g] - mx) * r;
    }
}

// ---------------- main kernel: one CTA per tree, g split 2-way ----------------
// Thread = (gh, node): gh = tid>>9, nd = tid & 511.
// smem map (u64 units):
//   bufA [0, 8192)      : [gh][c][512]  (levels 9,7,5,3,1)
//   bufB [8192, 12288)  : [gh][c][256]  (levels 8,6,4,2)
//   Bm_s [12288, 16384) : [gh][c][m]
//   A_s  [16384, 16640) : [p][gh][c][d]  (d contiguous -> LDS.128 pairs)
//   Pi_s [16640, 16672) : [p][gh][c]     (c contiguous -> LDS.128 pairs)
//   red  [16672, 16674) : 4 floats
#define SMEM_U64 16674
#define SMEM_BYTES (SMEM_U64 * 8)

__global__ __launch_bounds__(NTH) void htmm_main(const int* __restrict__ pos,
                                                 const int* __restrict__ x,
                                                 float* __restrict__ out) {
    extern __shared__ u64 smu[];
    float* red = (float*)(smu + 16672);

    const int t = blockIdx.x, tid = threadIdx.x;
    const int gh = tid >> 9, nd = tid & 511;

    // stage constants
    if (tid < 256) {
        // A_s[p][gh][c][d] <- g_A[c][d][p][2gh..]
        int d = tid & 7, c = (tid >> 3) & 7, ghs = (tid >> 6) & 1, p = tid >> 7;
        const float* src = &g_A[c][d][p][2 * ghs];
        smu[16384 + tid] = pk2f(src[0], src[1]);
    }
    for (int i = tid; i < 2048; i += NTH) {
        float4 f = ((const float4*)g_Bm)[i];
        smu[12288 + i] = pk2f(f.x, f.y);
        smu[14336 + i] = pk2f(f.z, f.w);
    }
    if (tid < 32) {
        int c = tid & 7, ghs = (tid >> 3) & 1, p = tid >> 4;
        const float* src = &g_Pi[p][c][2 * ghs];
        smu[16640 + tid] = pk2f(src[0], src[1]);
    }
    if (tid < 4) red[tid] = 0.f;
    __syncthreads();

    const u64* BmH = smu + 12288 + gh * 2048;                   // [c*256 + m]
    const ulonglong2* Abase = (const ulonglong2*)(smu + 16384); // 32 per (p,gh)
    const ulonglong2* Pibase = (const ulonglong2*)(smu + 16640);// 4 per (p,gh)
    u64* bufAh = smu + gh * 4096;
    u64* bufBh = smu + 8192 + gh * 2048;

    float llx = 0.f, lly = 0.f;
    const u64 ONE2 = pk2f(1.f, 1.f);

    // ---- fused levels 11 -> 10 -> 9 in registers ----
    {
        const int offL  = 128 * 2047 + (t << 11);
        const int off10 = 128 * 1023 + (t << 10);
        const int off9  = 128 * 511  + (t << 9);

        const int4 pL  = *(const int4*)(pos + offL + 4 * nd);
        const int4 xL  = *(const int4*)(x   + offL + 4 * nd);
        const int2 p10 = *(const int2*)(pos + off10 + 2 * nd);
        const int2 x10 = *(const int2*)(x   + off10 + 2 * nd);

        u64 acc9[8];
        u64 nuprodL = ONE2, nuprodU = ONE2;

#pragma unroll
        for (int s10 = 0; s10 < 2; s10++) {
            u64 acc10[8];
#pragma unroll
            for (int s11 = 0; s11 < 2; s11++) {
                int li = 2 * s10 + s11;
                int p = (li == 0) ? pL.x : (li == 1) ? pL.y : (li == 2) ? pL.z : pL.w;
                int m = (li == 0) ? xL.x : (li == 1) ? xL.y : (li == 2) ? xL.z : xL.w;
                const ulonglong2* Pi2 = Pibase + (p * 2 + gh) * 4;
                u64 b[8];
                u64 nu;
#pragma unroll
                for (int c2 = 0; c2 < 4; c2++) {
                    ulonglong2 pi = Pi2[c2];
                    b[2 * c2]     = mul2p(pi.x, BmH[(2 * c2) * 256 + m]);
                    b[2 * c2 + 1] = mul2p(pi.y, BmH[(2 * c2 + 1) * 256 + m]);
                    u64 pr = add2p(b[2 * c2], b[2 * c2 + 1]);
                    nu = (c2 == 0) ? pr : add2p(nu, pr);
                }
                nuprodL = mul2p(nuprodL, nu);
                float nx, ny; unpk2f(nu, nx, ny);
                u64 r = pk2f(__fdividef(1.f, nx), __fdividef(1.f, ny));
#pragma unroll
                for (int c = 0; c < 8; c++) b[c] = mul2p(b[c], r);
                matvec8(Abase + (p * 2 + gh) * 32, b, acc10, s11 != 0);
            }
            int m = (s10 == 0) ? x10.x : x10.y;
            int p = (s10 == 0) ? p10.x : p10.y;
            u64 nu;
#pragma unroll
            for (int c = 0; c < 8; c++) {
                acc10[c] = mul2p(acc10[c], BmH[c * 256 + m]);
                nu = (c == 0) ? acc10[0] : add2p(nu, acc10[c]);
            }
            nuprodU = mul2p(nuprodU, nu);
            float nx, ny; unpk2f(nu, nx, ny);
            u64 r = pk2f(__fdividef(1.f, nx), __fdividef(1.f, ny));
#pragma unroll
            for (int c = 0; c < 8; c++) acc10[c] = mul2p(acc10[c], r);
            matvec8(Abase + (p * 2 + gh) * 32, acc10, acc9, s10 != 0);
        }
        // level-9 node
        int m = x[off9 + nd];
        int p9 = pos[off9 + nd];
        u64 nu;
#pragma unroll
        for (int c = 0; c < 8; c++) {
            acc9[c] = mul2p(acc9[c], BmH[c * 256 + m]);
            nu = (c == 0) ? acc9[0] : add2p(nu, acc9[c]);
        }
        nuprodU = mul2p(nuprodU, nu);
        float nx, ny; unpk2f(nu, nx, ny);
        u64 r = pk2f(__fdividef(1.f, nx), __fdividef(1.f, ny));
#pragma unroll
        for (int c = 0; c < 8; c++) acc9[c] = mul2p(acc9[c], r);
        u64 msg[8];
        matvec8(Abase + (p9 * 2 + gh) * 32, acc9, msg, false);
#pragma unroll
        for (int c = 0; c < 8; c++) bufAh[c * 512 + nd] = msg[c];

        float ax, ay, bx, by;
        unpk2f(nuprodL, ax, ay);
        unpk2f(nuprodU, bx, by);
        llx += __logf(ax) + __logf(bx);
        lly += __logf(ay) + __logf(by);
    }
    __syncthreads();

    // ---- single-phase levels: l = child level (9,8,7) ----
#pragma unroll 1
    for (int l = 9; l >= 7; --l) {
        const int n_pa = 1 << (l - 1);            // 256, 128, 64
        u64* chb = (l & 1) ? bufAh : bufBh;
        const int csh = (l & 1) ? 256 : 128;
        u64* pb  = (l & 1) ? bufBh : bufAh;
        const int ps = (l & 1) ? 256 : 512;
        const int offP = 128 * ((1 << (l - 1)) - 1) + (t << (l - 1));

        if (nd < n_pa) {
            const int pa = nd;
            int m = x[offP + pa];
            int p = pos[offP + pa];
            const ulonglong2* ch2 = (const ulonglong2*)chb;
            u64 v[8];
            u64 nu;
#pragma unroll
            for (int c = 0; c < 8; c++) {
                ulonglong2 pr = ch2[c * csh + pa];
                v[c] = mul2p(add2p(pr.x, pr.y), BmH[c * 256 + m]);
                nu = (c == 0) ? v[0] : add2p(nu, v[c]);
            }
            float nx, ny; unpk2f(nu, nx, ny);
            llx += __logf(nx);
            lly += __logf(ny);
            u64 r = pk2f(__fdividef(1.f, nx), __fdividef(1.f, ny));
#pragma unroll
            for (int c = 0; c < 8; c++) v[c] = mul2p(v[c], r);
            u64 msg[8];
            matvec8(Abase + (p * 2 + gh) * 32, v, msg, false);
#pragma unroll
            for (int c = 0; c < 8; c++) pb[c * ps + pa] = msg[c];
        }
        __syncthreads();
    }

    // ---- tail: l = 6..1, two independent warps (one per gh) ----
    if (nd < 32) {
        float prodx = 1.f, prody = 1.f;
#pragma unroll 1
        for (int l = 6; l >= 1; --l) {
            const int n_pa = 1 << (l - 1);
            u64* chb = (l & 1) ? bufAh : bufBh;
            const int csh = (l & 1) ? 256 : 128;
            u64* pb  = (l & 1) ? bufBh : bufAh;
            const int ps = (l & 1) ? 256 : 512;
            const int offP = 128 * ((1 << (l - 1)) - 1) + (t << (l - 1));

            if (nd < n_pa) {
                const int pa = nd;
                int m = x[offP + pa];
                const ulonglong2* ch2 = (const ulonglong2*)chb;
                u64 v[8];
                u64 nu;
#pragma unroll
                for (int c = 0; c < 8; c++) {
                    ulonglong2 pr = ch2[c * csh + pa];
                    v[c] = mul2p(add2p(pr.x, pr.y), BmH[c * 256 + m]);
                    nu = (c == 0) ? v[0] : add2p(nu, v[c]);
                }
                float nx, ny; unpk2f(nu, nx, ny);
                prodx *= nx; prody *= ny;
                if (l > 1) {
                    int p = pos[offP + pa];
                    u64 r = pk2f(__fdividef(1.f, nx), __fdividef(1.f, ny));
#pragma unroll
                    for (int c = 0; c < 8; c++) v[c] = mul2p(v[c], r);
                    u64 msg[8];
                    matvec8(Abase + (p * 2 + gh) * 32, v, msg, false);
#pragma unroll
                    for (int c = 0; c < 8; c++) pb[c * ps + pa] = msg[c];
                }
            }
            __syncwarp();
        }
        llx += __logf(prodx);
        lly += __logf(prody);
    }

    // ---- reduction ----
#pragma unroll
    for (int o = 16; o; o >>= 1) {
        llx += __shfl_xor_sync(0xffffffffu, llx, o);
        lly += __shfl_xor_sync(0xffffffffu, lly, o);
    }
    if ((tid & 31) == 0) {
        atomicAdd(&red[2 * gh + 0], llx);
        atomicAdd(&red[2 * gh + 1], lly);
    }
    __syncthreads();
    if (tid < 4) out[t * 4 + tid] = red[tid];
}

extern "C" void kernel_launch(void* const* d_in, const int* in_sizes, int n_in,
                              void* d_out, int out_size) {
    const float* lA  = (const float*)d_in[0];
    const float* lB  = (const float*)d_in[1];
    const float* lPi = (const float*)d_in[2];
    const float* lSP = (const float*)d_in[3];
    const int*   pos = (const int*)d_in[4];
    const int*   x   = (const int*)d_in[5];
    float*       out = (float*)d_out;

    cudaFuncSetAttribute(htmm_main, cudaFuncAttributeMaxDynamicSharedMemorySize, SMEM_BYTES);

    htmm_precompute<<<1, 1024>>>(lA, lB, lPi, lSP);
    htmm_main<<<NTREES, NTH, SMEM_BYTES>>>(pos, x, out);
}

// round 7
// speedup vs baseline: 1.2749x; 1.2749x over previous
#include <cuda_runtime.h>

#define NTREES 128
#define C 8
#define L 2
#define M 256
#define G 4
#define NTH 1024

typedef unsigned long long u64;

// Precomputed (softmaxed) parameters. SP folded into A.
__device__ float g_A[C][C][L][G];   // [c][d][p][g]
__device__ float g_Bm[C][M][G];
__device__ float g_Pi[L][C][G];
// Leaf tables: message after normalize + A-transform, and log nu.
__device__ float2 g_Tmsg[2][C][512];   // [gh][c][p*256+m] -> (g=2gh, g=2gh+1)
__device__ float2 g_Tlog[2][512];      // [gh][p*256+m]

// ---------------- packed f32x2 helpers ----------------
static __device__ __forceinline__ u64 pk2f(float lo, float hi) {
    u64 r; asm("mov.b64 %0,{%1,%2};" : "=l"(r) : "f"(lo), "f"(hi)); return r;
}
static __device__ __forceinline__ void unpk2f(u64 v, float& lo, float& hi) {
    asm("mov.b64 {%0,%1},%2;" : "=f"(lo), "=f"(hi) : "l"(v));
}
static __device__ __forceinline__ u64 fma2p(u64 a, u64 b, u64 c) {
    u64 d; asm("fma.rn.f32x2 %0,%1,%2,%3;" : "=l"(d) : "l"(a), "l"(b), "l"(c)); return d;
}
static __device__ __forceinline__ u64 mul2p(u64 a, u64 b) {
    u64 d; asm("mul.rn.f32x2 %0,%1,%2;" : "=l"(d) : "l"(a), "l"(b)); return d;
}
static __device__ __forceinline__ u64 add2p(u64 a, u64 b) {
    u64 d; asm("add.rn.f32x2 %0,%1,%2;" : "=l"(d) : "l"(a), "l"(b)); return d;
}

// ---------------- precompute softmaxes (parallel) ----------------
__global__ void htmm_precompute(const float* __restrict__ lA, const float* __restrict__ lB,
                                const float* __restrict__ lPi, const float* __restrict__ lSP) {
    const int tid = threadIdx.x;
    const int wid = tid >> 5, lane = tid & 31;

    // Bm: one warp per (c,g)
    {
        int c = wid >> 2, g = wid & 3;
        float v[8];
        float mx = -1e30f;
#pragma unroll
        for (int j = 0; j < 8; j++) {
            int m = lane + 32 * j;
            v[j] = lB[(c * M + m) * G + g];
            mx = fmaxf(mx, v[j]);
        }
#pragma unroll
        for (int o = 16; o; o >>= 1) mx = fmaxf(mx, __shfl_xor_sync(0xffffffffu, mx, o));
        float s = 0.f;
#pragma unroll
        for (int j = 0; j < 8; j++) { v[j] = __expf(v[j] - mx); s += v[j]; }
#pragma unroll
        for (int o = 16; o; o >>= 1) s += __shfl_xor_sync(0xffffffffu, s, o);
        float r = 1.f / s;
#pragma unroll
        for (int j = 0; j < 8; j++) g_Bm[c][lane + 32 * j][g] = v[j] * r;
    }

    if (tid < 64) {
        int d = tid >> 3, p = (tid >> 2) & 1, g = tid & 3;
        float s0 = lSP[0 * G + g], s1 = lSP[1 * G + g];
        float mxs = fmaxf(s0, s1);
        float e0 = __expf(s0 - mxs), e1 = __expf(s1 - mxs);
        float sp = (p == 0 ? e0 : e1) / (e0 + e1);
        float mx = -1e30f;
#pragma unroll
        for (int c = 0; c < C; c++) mx = fmaxf(mx, lA[((c * C + d) * L + p) * G + g]);
        float s = 0.f;
#pragma unroll
        for (int c = 0; c < C; c++) s += __expf(lA[((c * C + d) * L + p) * G + g] - mx);
        float r = sp / s;
#pragma unroll
        for (int c = 0; c < C; c++)
            g_A[c][d][p][g] = __expf(lA[((c * C + d) * L + p) * G + g] - mx) * r;
    } else if (tid < 72) {
        int t2 = tid - 64;
        int p = t2 >> 2, g = t2 & 3;
        float mx = -1e30f;
#pragma unroll
        for (int c = 0; c < C; c++) mx = fmaxf(mx, lPi[(c * L + p) * G + g]);
        float s = 0.f;
#pragma unroll
        for (int c = 0; c < C; c++) s += __expf(lPi[(c * L + p) * G + g] - mx);
        float r = 1.f / s;
#pragma unroll
        for (int c = 0; c < C; c++) g_Pi[p][c][g] = __expf(lPi[(c * L + p) * G + g] - mx) * r;
    }
}

// ---------------- leaf-message table: one thread per (p,m) ----------------
__global__ void htmm_table() {
    const int pm = threadIdx.x;           // 512 threads
    const int p = pm >> 8, m = pm & 255;

    float b[C][G], nu[G], rr[G];
#pragma unroll
    for (int g = 0; g < G; g++) nu[g] = 0.f;
#pragma unroll
    for (int c = 0; c < C; c++)
#pragma unroll
        for (int g = 0; g < G; g++) {
            b[c][g] = g_Pi[p][c][g] * g_Bm[c][m][g];
            nu[g] += b[c][g];
        }
#pragma unroll
    for (int g = 0; g < G; g++) rr[g] = __fdividef(1.f, nu[g]);

    // logs
#pragma unroll
    for (int gh = 0; gh < 2; gh++)
        g_Tlog[gh][pm] = make_float2(__logf(nu[2 * gh]), __logf(nu[2 * gh + 1]));

    // msg[c][g] = sum_d A[c][d][p][g] * b[d][g] * rr[g]
#pragma unroll
    for (int c = 0; c < C; c++) {
        float mm[G];
#pragma unroll
        for (int g = 0; g < G; g++) mm[g] = 0.f;
#pragma unroll
        for (int d = 0; d < C; d++)
#pragma unroll
            for (int g = 0; g < G; g++) mm[g] = fmaf(g_A[c][d][p][g], b[d][g] * rr[g], mm[g]);
#pragma unroll
        for (int gh = 0; gh < 2; gh++)
            g_Tmsg[gh][c][pm] = make_float2(mm[2 * gh], mm[2 * gh + 1]);
    }
}

// ---------------- main kernel: one CTA per tree, g split 2-way ----------------
// Thread = (gh, node): gh = tid>>9, nd = tid & 511.
// smem map (u64 units):
//   bufA [0, 8192)       : [gh][c][512]  (levels 9,7,5,3,1)
//   bufB [8192, 12288)   : [gh][c][256]  (levels 8,6,4,2)
//   Bm_s [12288, 16384)  : [gh][c][m]
//   A_s  [16384, 16640)  : [c][d][p][gh]  (p-variants 16B apart -> distinct banks)
//   Tmsg [16640, 24832)  : [gh][c][pm]
//   Tlog [24832, 25856)  : [gh][pm]
//   red  [25856, 25858)  : 4 floats
#define SMEM_U64 25858
#define SMEM_BYTES (SMEM_U64 * 8)

__global__ __launch_bounds__(NTH) void htmm_main(const int* __restrict__ pos,
                                                 const int* __restrict__ x,
                                                 float* __restrict__ out) {
    extern __shared__ u64 smu[];
    float* red = (float*)(smu + 25856);

    const int t = blockIdx.x, tid = threadIdx.x;
    const int gh = tid >> 9, nd = tid & 511;

    // stage constants
    if (tid < 128) {
        float4 f = ((const float4*)g_A)[tid];
        smu[16384 + 2 * tid]     = pk2f(f.x, f.y);
        smu[16384 + 2 * tid + 1] = pk2f(f.z, f.w);
    }
    for (int i = tid; i < 2048; i += NTH) {
        float4 f = ((const float4*)g_Bm)[i];
        smu[12288 + i] = pk2f(f.x, f.y);
        smu[14336 + i] = pk2f(f.z, f.w);
    }
    for (int i = tid; i < 8192; i += NTH) smu[16640 + i] = ((const u64*)g_Tmsg)[i];
    if (tid < 1024) smu[24832 + tid] = ((const u64*)g_Tlog)[tid];
    if (tid < 4) red[tid] = 0.f;
    __syncthreads();

    const u64* BmH   = smu + 12288 + gh * 2048;   // [c*256 + m]
    const u64* A0    = smu + 16384 + gh;          // [(c*8+d)*4 + p*2]
    const u64* TmsgH = smu + 16640 + gh * 4096;   // [c*512 + pm]
    const u64* TlogH = smu + 24832 + gh * 512;    // [pm]
    u64* bufAh = smu + gh * 4096;
    u64* bufBh = smu + 8192 + gh * 2048;

    float llx = 0.f, lly = 0.f;
    const u64 ONE2 = pk2f(1.f, 1.f);

    // ---- fused levels 11 (table lookup) -> 10 -> 9 in registers ----
    {
        const int offL  = 128 * 2047 + (t << 11);
        const int off10 = 128 * 1023 + (t << 10);
        const int off9  = 128 * 511  + (t << 9);

        const int4 pL  = *(const int4*)(pos + offL + 4 * nd);
        const int4 xL  = *(const int4*)(x   + offL + 4 * nd);
        const int2 p10 = *(const int2*)(pos + off10 + 2 * nd);
        const int2 x10 = *(const int2*)(x   + off10 + 2 * nd);

        const int pm0 = pL.x * 256 + xL.x, pm1 = pL.y * 256 + xL.y;
        const int pm2 = pL.z * 256 + xL.z, pm3 = pL.w * 256 + xL.w;

        // leaf log-nus straight from table
        u64 llleaf = add2p(add2p(TlogH[pm0], TlogH[pm1]), add2p(TlogH[pm2], TlogH[pm3]));

        u64 acc9[8];
        u64 nuprodU = ONE2;

#pragma unroll
        for (int s10 = 0; s10 < 2; s10++) {
            const int pma = (s10 == 0) ? pm0 : pm2;
            const int pmb = (s10 == 0) ? pm1 : pm3;
            u64 acc10[8];
#pragma unroll
            for (int c = 0; c < 8; c++)
                acc10[c] = add2p(TmsgH[c * 512 + pma], TmsgH[c * 512 + pmb]);

            int m = (s10 == 0) ? x10.x : x10.y;
            int p = (s10 == 0) ? p10.x : p10.y;
            u64 nu;
#pragma unroll
            for (int c = 0; c < 8; c++) {
                acc10[c] = mul2p(acc10[c], BmH[c * 256 + m]);
                nu = (c == 0) ? acc10[0] : add2p(nu, acc10[c]);
            }
            nuprodU = mul2p(nuprodU, nu);
            float nx, ny; unpk2f(nu, nx, ny);
            u64 r = pk2f(__fdividef(1.f, nx), __fdividef(1.f, ny));
#pragma unroll
            for (int c = 0; c < 8; c++) acc10[c] = mul2p(acc10[c], r);
            const u64* Ap = A0 + p * 2;
#pragma unroll
            for (int c = 0; c < 8; c++) {
                u64 mm = (s10 == 0) ? 0ull : acc9[c];
#pragma unroll
                for (int d = 0; d < 8; d++) mm = fma2p(Ap[(c * 8 + d) * 4], acc10[d], mm);
                acc9[c] = mm;
            }
        }
        // level-9 node
        int m = x[off9 + nd];
        int p9 = pos[off9 + nd];
        u64 nu;
#pragma unroll
        for (int c = 0; c < 8; c++) {
            acc9[c] = mul2p(acc9[c], BmH[c * 256 + m]);
            nu = (c == 0) ? acc9[0] : add2p(nu, acc9[c]);
        }
        nuprodU = mul2p(nuprodU, nu);
        float nx, ny; unpk2f(nu, nx, ny);
        u64 r = pk2f(__fdividef(1.f, nx), __fdividef(1.f, ny));
#pragma unroll
        for (int c = 0; c < 8; c++) acc9[c] = mul2p(acc9[c], r);
        const u64* Ap = A0 + p9 * 2;
#pragma unroll
        for (int c = 0; c < 8; c++) {
            u64 mm = 0ull;
#pragma unroll
            for (int d = 0; d < 8; d++) mm = fma2p(Ap[(c * 8 + d) * 4], acc9[d], mm);
            bufAh[c * 512 + nd] = mm;
        }

        float ax, ay, bx, by;
        unpk2f(llleaf, ax, ay);
        unpk2f(nuprodU, bx, by);
        llx += ax + __logf(bx);
        lly += ay + __logf(by);
    }
    __syncthreads();

    // ---- single-phase levels: l = child level (9,8,7) ----
#pragma unroll 1
    for (int l = 9; l >= 7; --l) {
        const int n_pa = 1 << (l - 1);            // 256, 128, 64
        u64* chb = (l & 1) ? bufAh : bufBh;
        const int csh = (l & 1) ? 256 : 128;
        u64* pb  = (l & 1) ? bufBh : bufAh;
        const int ps = (l & 1) ? 256 : 512;
        const int offP = 128 * ((1 << (l - 1)) - 1) + (t << (l - 1));

        if (nd < n_pa) {
            const int pa = nd;
            int m = x[offP + pa];
            int p = pos[offP + pa];
            const ulonglong2* ch2 = (const ulonglong2*)chb;
            u64 v[8];
            u64 nu;
#pragma unroll
            for (int c = 0; c < 8; c++) {
                ulonglong2 pr = ch2[c * csh + pa];
                v[c] = mul2p(add2p(pr.x, pr.y), BmH[c * 256 + m]);
                nu = (c == 0) ? v[0] : add2p(nu, v[c]);
            }
            float nx, ny; unpk2f(nu, nx, ny);
            llx += __logf(nx);
            lly += __logf(ny);
            u64 r = pk2f(__fdividef(1.f, nx), __fdividef(1.f, ny));
#pragma unroll
            for (int c = 0; c < 8; c++) v[c] = mul2p(v[c], r);
            const u64* Ap = A0 + p * 2;
#pragma unroll
            for (int c = 0; c < 8; c++) {
                u64 mm = 0ull;
#pragma unroll
                for (int d = 0; d < 8; d++) mm = fma2p(Ap[(c * 8 + d) * 4], v[d], mm);
                pb[c * ps + pa] = mm;
            }
        }
        __syncthreads();
    }

    // ---- tail: l = 6..1, two independent warps (one per gh) ----
    if (nd < 32) {
        float prodx = 1.f, prody = 1.f;
#pragma unroll 1
        for (int l = 6; l >= 1; --l) {
            const int n_pa = 1 << (l - 1);
            u64* chb = (l & 1) ? bufAh : bufBh;
            const int csh = (l & 1) ? 256 : 128;
            u64* pb  = (l & 1) ? bufBh : bufAh;
            const int ps = (l & 1) ? 256 : 512;
            const int offP = 128 * ((1 << (l - 1)) - 1) + (t << (l - 1));

            if (nd < n_pa) {
                const int pa = nd;
                int m = x[offP + pa];
                const ulonglong2* ch2 = (const ulonglong2*)chb;
                u64 v[8];
                u64 nu;
#pragma unroll
                for (int c = 0; c < 8; c++) {
                    ulonglong2 pr = ch2[c * csh + pa];
                    v[c] = mul2p(add2p(pr.x, pr.y), BmH[c * 256 + m]);
                    nu = (c == 0) ? v[0] : add2p(nu, v[c]);
                }
                float nx, ny; unpk2f(nu, nx, ny);
                prodx *= nx; prody *= ny;
                if (l > 1) {
                    int p = pos[offP + pa];
                    u64 r = pk2f(__fdividef(1.f, nx), __fdividef(1.f, ny));
#pragma unroll
                    for (int c = 0; c < 8; c++) v[c] = mul2p(v[c], r);
                    const u64* Ap = A0 + p * 2;
#pragma unroll
                    for (int c = 0; c < 8; c++) {
                        u64 mm = 0ull;
#pragma unroll
                        for (int d = 0; d < 8; d++) mm = fma2p(Ap[(c * 8 + d) * 4], v[d], mm);
                        pb[c * ps + pa] = mm;
                    }
                }
            }
            __syncwarp();
        }
        llx += __logf(prodx);
        lly += __logf(prody);
    }

    // ---- reduction ----
#pragma unroll
    for (int o = 16; o; o >>= 1) {
        llx += __shfl_xor_sync(0xffffffffu, llx, o);
        lly += __shfl_xor_sync(0xffffffffu, lly, o);
    }
    if ((tid & 31) == 0) {
        atomicAdd(&red[2 * gh + 0], llx);
        atomicAdd(&red[2 * gh + 1], lly);
    }
    __syncthreads();
    if (tid < 4) out[t * 4 + tid] = red[tid];
}

extern "C" void kernel_launch(void* const* d_in, const int* in_sizes, int n_in,
                              void* d_out, int out_size) {
    const float* lA  = (const float*)d_in[0];
    const float* lB  = (const float*)d_in[1];
    const float* lPi = (const float*)d_in[2];
    const float* lSP = (const float*)d_in[3];
    const int*   pos = (const int*)d_in[4];
    const int*   x   = (const int*)d_in[5];
    float*       out = (float*)d_out;

    cudaFuncSetAttribute(htmm_main, cudaFuncAttributeMaxDynamicSharedMemorySize, SMEM_BYTES);

    htmm_precompute<<<1, 1024>>>(lA, lB, lPi, lSP);
    htmm_table<<<1, 512>>>();
    htmm_main<<<NTREES, NTH, SMEM_BYTES>>>(pos, x, out);
}

// round 8
// speedup vs baseline: 1.8977x; 1.4886x over previous
#include <cuda_runtime.h>

#define NTREES 128
#define C 8
#define L 2
#define M 256
#define G 4
#define NTH 1024

typedef unsigned long long u64;

// ---------------- packed f32x2 helpers ----------------
static __device__ __forceinline__ u64 pk2f(float lo, float hi) {
    u64 r; asm("mov.b64 %0,{%1,%2};" : "=l"(r) : "f"(lo), "f"(hi)); return r;
}
static __device__ __forceinline__ void unpk2f(u64 v, float& lo, float& hi) {
    asm("mov.b64 {%0,%1},%2;" : "=f"(lo), "=f"(hi) : "l"(v));
}
static __device__ __forceinline__ u64 fma2p(u64 a, u64 b, u64 c) {
    u64 d; asm("fma.rn.f32x2 %0,%1,%2,%3;" : "=l"(d) : "l"(a), "l"(b), "l"(c)); return d;
}
static __device__ __forceinline__ u64 mul2p(u64 a, u64 b) {
    u64 d; asm("mul.rn.f32x2 %0,%1,%2;" : "=l"(d) : "l"(a), "l"(b)); return d;
}
static __device__ __forceinline__ u64 add2p(u64 a, u64 b) {
    u64 d; asm("add.rn.f32x2 %0,%1,%2;" : "=l"(d) : "l"(a), "l"(b)); return d;
}

// ---------------- single fused kernel: one CTA per tree ----------------
// smem map (u64 units):
//   bufA [0, 8192)       : [gh][c][512]  (levels 9,7,5,3,1)
//   bufB [8192, 12288)   : [gh][c][256]  (levels 8,6,4,2)
//   Bm_s [12288, 16384)  : [gh][c][m]
//   A_s  [16384, 16640)  : [c][d][p][gh]  (p-variants 16B apart -> distinct banks)
//   Tmsg [16640, 24832)  : [gh][c][pm]
//   Tlog [24832, 25856)  : [gh][pm]
//   Pi_s [25856, 25888)  : [p][c][gh]
//   red  [25888, 25890)  : 4 floats
#define SMEM_U64 25890
#define SMEM_BYTES (SMEM_U64 * 8)

__global__ __launch_bounds__(NTH) void htmm_main(const float* __restrict__ lA,
                                                 const float* __restrict__ lB,
                                                 const float* __restrict__ lPi,
                                                 const float* __restrict__ lSP,
                                                 const int* __restrict__ pos,
                                                 const int* __restrict__ x,
                                                 float* __restrict__ out) {
    extern __shared__ u64 smu[];
    float* red = (float*)(smu + 25888);

    const int t = blockIdx.x, tid = threadIdx.x;
    const int gh = tid >> 9, nd = tid & 511;
    const int wid = tid >> 5, lane = tid & 31;

    // ========== per-CTA prologue 1: softmaxes into smem ==========
    // Bm: one warp per (c,g); lane handles 8 m's
    {
        int c = wid >> 2, g = wid & 3;
        float v[8];
        float mx = -1e30f;
#pragma unroll
        for (int j = 0; j < 8; j++) {
            v[j] = lB[(c * M + lane + 32 * j) * G + g];
            mx = fmaxf(mx, v[j]);
        }
#pragma unroll
        for (int o = 16; o; o >>= 1) mx = fmaxf(mx, __shfl_xor_sync(0xffffffffu, mx, o));
        float s = 0.f;
#pragma unroll
        for (int j = 0; j < 8; j++) { v[j] = __expf(v[j] - mx); s += v[j]; }
#pragma unroll
        for (int o = 16; o; o >>= 1) s += __shfl_xor_sync(0xffffffffu, s, o);
        float r = 1.f / s;
        float* BmF = (float*)(smu + 12288);
        int ghw = g >> 1, lo = g & 1;
#pragma unroll
        for (int j = 0; j < 8; j++)
            BmF[(ghw * 2048 + c * 256 + lane + 32 * j) * 2 + lo] = v[j] * r;
    }
    // A softmax over c per (d,p,g), fold SP[p,g]  (64 threads)
    if (tid < 64) {
        int d = tid >> 3, p = (tid >> 2) & 1, g = tid & 3;
        float s0 = lSP[0 * G + g], s1 = lSP[1 * G + g];
        float mxs = fmaxf(s0, s1);
        float e0 = __expf(s0 - mxs), e1 = __expf(s1 - mxs);
        float sp = (p == 0 ? e0 : e1) / (e0 + e1);
        float mx = -1e30f;
#pragma unroll
        for (int c = 0; c < C; c++) mx = fmaxf(mx, lA[((c * C + d) * L + p) * G + g]);
        float s = 0.f;
#pragma unroll
        for (int c = 0; c < C; c++) s += __expf(lA[((c * C + d) * L + p) * G + g] - mx);
        float r = sp / s;
        float* AF = (float*)(smu + 16384);   // idx (c*8+d)*8 + p*4 + g
#pragma unroll
        for (int c = 0; c < C; c++)
            AF[(c * 8 + d) * 8 + p * 4 + g] = __expf(lA[((c * C + d) * L + p) * G + g] - mx) * r;
    } else if (tid < 72) {
        int t2 = tid - 64;
        int p = t2 >> 2, g = t2 & 3;
        float mx = -1e30f;
#pragma unroll
        for (int c = 0; c < C; c++) mx = fmaxf(mx, lPi[(c * L + p) * G + g]);
        float s = 0.f;
#pragma unroll
        for (int c = 0; c < C; c++) s += __expf(lPi[(c * L + p) * G + g] - mx);
        float r = 1.f / s;
        float* PiF = (float*)(smu + 25856);  // idx p*32 + c*4 + g
#pragma unroll
        for (int c = 0; c < C; c++)
            PiF[p * 32 + c * 4 + g] = __expf(lPi[(c * L + p) * G + g] - mx) * r;
    }
    if (tid < 4) red[tid] = 0.f;
    __syncthreads();

    // ========== per-CTA prologue 2: leaf table (thread = (pm, gh)) ==========
    {
        const int pm = tid & 511, ghb = tid >> 9;
        const int p = pm >> 8, m = pm & 255;
        const u64* BmG = smu + 12288 + ghb * 2048;
        u64 b[8], nu;
#pragma unroll
        for (int c = 0; c < 8; c++) {
            b[c] = mul2p(smu[25856 + p * 16 + c * 2 + ghb], BmG[c * 256 + m]);
            nu = (c == 0) ? b[0] : add2p(nu, b[c]);
        }
        float nx, ny; unpk2f(nu, nx, ny);
        smu[24832 + ghb * 512 + pm] = pk2f(__logf(nx), __logf(ny));
        u64 r = pk2f(__fdividef(1.f, nx), __fdividef(1.f, ny));
#pragma unroll
        for (int c = 0; c < 8; c++) b[c] = mul2p(b[c], r);
        const u64* Ab = smu + 16384 + ghb;   // [(c*8+d)*4 + p*2]
#pragma unroll
        for (int c = 0; c < 8; c++) {
            u64 mm = 0ull;
#pragma unroll
            for (int d = 0; d < 8; d++) mm = fma2p(Ab[(c * 8 + d) * 4 + p * 2], b[d], mm);
            smu[16640 + ghb * 4096 + c * 512 + pm] = mm;
        }
    }
    __syncthreads();

    const u64* BmH   = smu + 12288 + gh * 2048;   // [c*256 + m]
    const u64* A0    = smu + 16384 + gh;          // [(c*8+d)*4 + p*2]
    const u64* TmsgH = smu + 16640 + gh * 4096;   // [c*512 + pm]
    const u64* TlogH = smu + 24832 + gh * 512;    // [pm]
    u64* bufAh = smu + gh * 4096;
    u64* bufBh = smu + 8192 + gh * 2048;

    float llx = 0.f, lly = 0.f;
    const u64 ONE2 = pk2f(1.f, 1.f);

    // ---- fused levels 11 (table lookup) -> 10 -> 9 in registers ----
    {
        const int offL  = 128 * 2047 + (t << 11);
        const int off10 = 128 * 1023 + (t << 10);
        const int off9  = 128 * 511  + (t << 9);

        const int4 pL  = *(const int4*)(pos + offL + 4 * nd);
        const int4 xL  = *(const int4*)(x   + offL + 4 * nd);
        const int2 p10 = *(const int2*)(pos + off10 + 2 * nd);
        const int2 x10 = *(const int2*)(x   + off10 + 2 * nd);

        const int pm0 = pL.x * 256 + xL.x, pm1 = pL.y * 256 + xL.y;
        const int pm2 = pL.z * 256 + xL.z, pm3 = pL.w * 256 + xL.w;

        u64 llleaf = add2p(add2p(TlogH[pm0], TlogH[pm1]), add2p(TlogH[pm2], TlogH[pm3]));

        u64 acc9[8];
        u64 nuprodU = ONE2;

#pragma unroll
        for (int s10 = 0; s10 < 2; s10++) {
            const int pma = (s10 == 0) ? pm0 : pm2;
            const int pmb = (s10 == 0) ? pm1 : pm3;
            u64 acc10[8];
#pragma unroll
            for (int c = 0; c < 8; c++)
                acc10[c] = add2p(TmsgH[c * 512 + pma], TmsgH[c * 512 + pmb]);

            int m = (s10 == 0) ? x10.x : x10.y;
            int p = (s10 == 0) ? p10.x : p10.y;
            u64 nu;
#pragma unroll
            for (int c = 0; c < 8; c++) {
                acc10[c] = mul2p(acc10[c], BmH[c * 256 + m]);
                nu = (c == 0) ? acc10[0] : add2p(nu, acc10[c]);
            }
            nuprodU = mul2p(nuprodU, nu);
            float nx, ny; unpk2f(nu, nx, ny);
            u64 r = pk2f(__fdividef(1.f, nx), __fdividef(1.f, ny));
#pragma unroll
            for (int c = 0; c < 8; c++) acc10[c] = mul2p(acc10[c], r);
            const u64* Ap = A0 + p * 2;
#pragma unroll
            for (int c = 0; c < 8; c++) {
                u64 mm = (s10 == 0) ? 0ull : acc9[c];
#pragma unroll
                for (int d = 0; d < 8; d++) mm = fma2p(Ap[(c * 8 + d) * 4], acc10[d], mm);
                acc9[c] = mm;
            }
        }
        // level-9 node
        int m = x[off9 + nd];
        int p9 = pos[off9 + nd];
        u64 nu;
#pragma unroll
        for (int c = 0; c < 8; c++) {
            acc9[c] = mul2p(acc9[c], BmH[c * 256 + m]);
            nu = (c == 0) ? acc9[0] : add2p(nu, acc9[c]);
        }
        nuprodU = mul2p(nuprodU, nu);
        float nx, ny; unpk2f(nu, nx, ny);
        u64 r = pk2f(__fdividef(1.f, nx), __fdividef(1.f, ny));
#pragma unroll
        for (int c = 0; c < 8; c++) acc9[c] = mul2p(acc9[c], r);
        const u64* Ap = A0 + p9 * 2;
#pragma unroll
        for (int c = 0; c < 8; c++) {
            u64 mm = 0ull;
#pragma unroll
            for (int d = 0; d < 8; d++) mm = fma2p(Ap[(c * 8 + d) * 4], acc9[d], mm);
            bufAh[c * 512 + nd] = mm;
        }

        float ax, ay, bx, by;
        unpk2f(llleaf, ax, ay);
        unpk2f(nuprodU, bx, by);
        llx += ax + __logf(bx);
        lly += ay + __logf(by);
    }
    __syncthreads();

    // ---- single-phase levels: l = child level (9,8,7) ----
#pragma unroll 1
    for (int l = 9; l >= 7; --l) {
        const int n_pa = 1 << (l - 1);            // 256, 128, 64
        u64* chb = (l & 1) ? bufAh : bufBh;
        const int csh = (l & 1) ? 256 : 128;
        u64* pb  = (l & 1) ? bufBh : bufAh;
        const int ps = (l & 1) ? 256 : 512;
        const int offP = 128 * ((1 << (l - 1)) - 1) + (t << (l - 1));

        if (nd < n_pa) {
            const int pa = nd;
            int m = x[offP + pa];
            int p = pos[offP + pa];
            const ulonglong2* ch2 = (const ulonglong2*)chb;
            u64 v[8];
            u64 nu;
#pragma unroll
            for (int c = 0; c < 8; c++) {
                ulonglong2 pr = ch2[c * csh + pa];
                v[c] = mul2p(add2p(pr.x, pr.y), BmH[c * 256 + m]);
                nu = (c == 0) ? v[0] : add2p(nu, v[c]);
            }
            float nx, ny; unpk2f(nu, nx, ny);
            llx += __logf(nx);
            lly += __logf(ny);
            u64 r = pk2f(__fdividef(1.f, nx), __fdividef(1.f, ny));
#pragma unroll
            for (int c = 0; c < 8; c++) v[c] = mul2p(v[c], r);
            const u64* Ap = A0 + p * 2;
#pragma unroll
            for (int c = 0; c < 8; c++) {
                u64 mm = 0ull;
#pragma unroll
                for (int d = 0; d < 8; d++) mm = fma2p(Ap[(c * 8 + d) * 4], v[d], mm);
                pb[c * ps + pa] = mm;
            }
        }
        __syncthreads();
    }

    // ---- tail: l = 6..1, two independent warps (one per gh) ----
    if (nd < 32) {
        float prodx = 1.f, prody = 1.f;
#pragma unroll 1
        for (int l = 6; l >= 1; --l) {
            const int n_pa = 1 << (l - 1);
            u64* chb = (l & 1) ? bufAh : bufBh;
            const int csh = (l & 1) ? 256 : 128;
            u64* pb  = (l & 1) ? bufBh : bufAh;
            const int ps = (l & 1) ? 256 : 512;
            const int offP = 128 * ((1 << (l - 1)) - 1) + (t << (l - 1));

            if (nd < n_pa) {
                const int pa = nd;
                int m = x[offP + pa];
                const ulonglong2* ch2 = (const ulonglong2*)chb;
                u64 v[8];
                u64 nu;
#pragma unroll
                for (int c = 0; c < 8; c++) {
                    ulonglong2 pr = ch2[c * csh + pa];
                    v[c] = mul2p(add2p(pr.x, pr.y), BmH[c * 256 + m]);
                    nu = (c == 0) ? v[0] : add2p(nu, v[c]);
                }
                float nx, ny; unpk2f(nu, nx, ny);
                prodx *= nx; prody *= ny;
                if (l > 1) {
                    int p = pos[offP + pa];
                    u64 r = pk2f(__fdividef(1.f, nx), __fdividef(1.f, ny));
#pragma unroll
                    for (int c = 0; c < 8; c++) v[c] = mul2p(v[c], r);
                    const u64* Ap = A0 + p * 2;
#pragma unroll
                    for (int c = 0; c < 8; c++) {
                        u64 mm = 0ull;
#pragma unroll
                        for (int d = 0; d < 8; d++) mm = fma2p(Ap[(c * 8 + d) * 4], v[d], mm);
                        pb[c * ps + pa] = mm;
                    }
                }
            }
            __syncwarp();
        }
        llx += __logf(prodx);
        lly += __logf(prody);
    }

    // ---- reduction ----
#pragma unroll
    for (int o = 16; o; o >>= 1) {
        llx += __shfl_xor_sync(0xffffffffu, llx, o);
        lly += __shfl_xor_sync(0xffffffffu, lly, o);
    }
    if ((tid & 31) == 0) {
        atomicAdd(&red[2 * gh + 0], llx);
        atomicAdd(&red[2 * gh + 1], lly);
    }
    __syncthreads();
    if (tid < 4) out[t * 4 + tid] = red[tid];
}

extern "C" void kernel_launch(void* const* d_in, const int* in_sizes, int n_in,
                              void* d_out, int out_size) {
    const float* lA  = (const float*)d_in[0];
    const float* lB  = (const float*)d_in[1];
    const float* lPi = (const float*)d_in[2];
    const float* lSP = (const float*)d_in[3];
    const int*   pos = (const int*)d_in[4];
    const int*   x   = (const int*)d_in[5];
    float*       out = (float*)d_out;

    cudaFuncSetAttribute(htmm_main, cudaFuncAttributeMaxDynamicSharedMemorySize, SMEM_BYTES);

    htmm_main<<<NTREES, NTH, SMEM_BYTES>>>(lA, lB, lPi, lSP, pos, x, out);
}

// round 9
// speedup vs baseline: 1.9228x; 1.0132x over previous
#include <cuda_runtime.h>

#define NTREES 128
#define C 8
#define L 2
#define M 256
#define G 4
#define NTH 1024

typedef unsigned long long u64;

// ---------------- packed f32x2 helpers ----------------
static __device__ __forceinline__ u64 pk2f(float lo, float hi) {
    u64 r; asm("mov.b64 %0,{%1,%2};" : "=l"(r) : "f"(lo), "f"(hi)); return r;
}
static __device__ __forceinline__ void unpk2f(u64 v, float& lo, float& hi) {
    asm("mov.b64 {%0,%1},%2;" : "=f"(lo), "=f"(hi) : "l"(v));
}
static __device__ __forceinline__ u64 fma2p(u64 a, u64 b, u64 c) {
    u64 d; asm("fma.rn.f32x2 %0,%1,%2,%3;" : "=l"(d) : "l"(a), "l"(b), "l"(c)); return d;
}
static __device__ __forceinline__ u64 mul2p(u64 a, u64 b) {
    u64 d; asm("mul.rn.f32x2 %0,%1,%2;" : "=l"(d) : "l"(a), "l"(b)); return d;
}
static __device__ __forceinline__ u64 add2p(u64 a, u64 b) {
    u64 d; asm("add.rn.f32x2 %0,%1,%2;" : "=l"(d) : "l"(a), "l"(b)); return d;
}

// 8x8 matvec: A as ulonglong2 pairs over d. Ap pre-offset by (p*2 + gh);
// entry stride per (c,d2) is 4 ulonglong2. 32 LDS.128 instead of 64 LDS.64.
static __device__ __forceinline__ void matvec8p(const ulonglong2* __restrict__ Ap,
                                                const u64* __restrict__ b,
                                                u64* __restrict__ o, bool acc) {
#pragma unroll
    for (int c = 0; c < 8; c++) {
        u64 mm = acc ? o[c] : 0ull;
#pragma unroll
        for (int d2 = 0; d2 < 4; d2++) {
            ulonglong2 a = Ap[(c * 4 + d2) * 4];
            mm = fma2p(a.x, b[2 * d2], mm);
            mm = fma2p(a.y, b[2 * d2 + 1], mm);
        }
        o[c] = mm;
    }
}

// ---------------- single fused kernel: one CTA per tree ----------------
// smem map (u64 units):
//   bufA [0, 8192)       : [gh][c][512]  (levels 9,7,5,3,1)
//   bufB [8192, 12288)   : [gh][c][256]  (levels 8,6,4,2)
//   Bm_s [12288, 16384)  : [gh][c][m]
//   A_s  [16384, 16640)  : ulonglong2[c][d2][p][gh]  (d-pairs 16B; p-variants 32B apart)
//   Tmsg [16640, 24832)  : [gh][c][pm]
//   Tlog [24832, 25856)  : [gh][pm]
//   Pi_s [25856, 25888)  : [p][c][gh]
//   red  [25888, 25890)  : 4 floats
#define SMEM_U64 25890
#define SMEM_BYTES (SMEM_U64 * 8)

__global__ __launch_bounds__(NTH) void htmm_main(const float* __restrict__ lA,
                                                 const float* __restrict__ lB,
                                                 const float* __restrict__ lPi,
                                                 const float* __restrict__ lSP,
                                                 const int* __restrict__ pos,
                                                 const int* __restrict__ x,
                                                 float* __restrict__ out) {
    extern __shared__ u64 smu[];
    float* red = (float*)(smu + 25888);

    const int t = blockIdx.x, tid = threadIdx.x;
    const int gh = tid >> 9, nd = tid & 511;
    const int wid = tid >> 5, lane = tid & 31;

    // ========== per-CTA prologue 1: softmaxes into smem ==========
    // Bm: one warp per (c,g); lane handles 8 m's
    {
        int c = wid >> 2, g = wid & 3;
        float v[8];
        float mx = -1e30f;
#pragma unroll
        for (int j = 0; j < 8; j++) {
            v[j] = lB[(c * M + lane + 32 * j) * G + g];
            mx = fmaxf(mx, v[j]);
        }
#pragma unroll
        for (int o = 16; o; o >>= 1) mx = fmaxf(mx, __shfl_xor_sync(0xffffffffu, mx, o));
        float s = 0.f;
#pragma unroll
        for (int j = 0; j < 8; j++) { v[j] = __expf(v[j] - mx); s += v[j]; }
#pragma unroll
        for (int o = 16; o; o >>= 1) s += __shfl_xor_sync(0xffffffffu, s, o);
        float r = 1.f / s;
        float* BmF = (float*)(smu + 12288);
        int ghw = g >> 1, lo = g & 1;
#pragma unroll
        for (int j = 0; j < 8; j++)
            BmF[(ghw * 2048 + c * 256 + lane + 32 * j) * 2 + lo] = v[j] * r;
    }
    // A softmax over c per (d,p,g), fold SP[p,g]  (64 threads)
    if (tid < 64) {
        int d = tid >> 3, p = (tid >> 2) & 1, g = tid & 3;
        float s0 = lSP[0 * G + g], s1 = lSP[1 * G + g];
        float mxs = fmaxf(s0, s1);
        float e0 = __expf(s0 - mxs), e1 = __expf(s1 - mxs);
        float sp = (p == 0 ? e0 : e1) / (e0 + e1);
        float mx = -1e30f;
#pragma unroll
        for (int c = 0; c < C; c++) mx = fmaxf(mx, lA[((c * C + d) * L + p) * G + g]);
        float s = 0.f;
#pragma unroll
        for (int c = 0; c < C; c++) s += __expf(lA[((c * C + d) * L + p) * G + g] - mx);
        float r = sp / s;
        // A_s2 float layout: ((((c*4+d2)*2+p)*2+gh)*2 + (d&1))*2 + (g&1)
        float* AF = (float*)(smu + 16384);
        int d2 = d >> 1, dl = d & 1, ghx = g >> 1, gl = g & 1;
#pragma unroll
        for (int c = 0; c < C; c++) {
            int fi = ((((c * 4 + d2) * 2 + p) * 2 + ghx) * 2 + dl) * 2 + gl;
            AF[fi] = __expf(lA[((c * C + d) * L + p) * G + g] - mx) * r;
        }
    } else if (tid < 72) {
        int t2 = tid - 64;
        int p = t2 >> 2, g = t2 & 3;
        float mx = -1e30f;
#pragma unroll
        for (int c = 0; c < C; c++) mx = fmaxf(mx, lPi[(c * L + p) * G + g]);
        float s = 0.f;
#pragma unroll
        for (int c = 0; c < C; c++) s += __expf(lPi[(c * L + p) * G + g] - mx);
        float r = 1.f / s;
        float* PiF = (float*)(smu + 25856);  // idx p*32 + c*4 + g
#pragma unroll
        for (int c = 0; c < C; c++)
            PiF[p * 32 + c * 4 + g] = __expf(lPi[(c * L + p) * G + g] - mx) * r;
    }
    if (tid < 4) red[tid] = 0.f;
    __syncthreads();

    const ulonglong2* A2 = (const ulonglong2*)(smu + 16384);  // [ (c*4+d2)*4 + p*2 + gh ]

    // ========== per-CTA prologue 2: leaf table (thread = (pm, gh)) ==========
    {
        const int pm = tid & 511, ghb = tid >> 9;
        const int p = pm >> 8, m = pm & 255;
        const u64* BmG = smu + 12288 + ghb * 2048;
        u64 b[8], nu;
#pragma unroll
        for (int c = 0; c < 8; c++) {
            b[c] = mul2p(smu[25856 + p * 16 + c * 2 + ghb], BmG[c * 256 + m]);
            nu = (c == 0) ? b[0] : add2p(nu, b[c]);
        }
        float nx, ny; unpk2f(nu, nx, ny);
        smu[24832 + ghb * 512 + pm] = pk2f(__logf(nx), __logf(ny));
        u64 r = pk2f(__fdividef(1.f, nx), __fdividef(1.f, ny));
#pragma unroll
        for (int c = 0; c < 8; c++) b[c] = mul2p(b[c], r);
        u64 msg[8];
        matvec8p(A2 + p * 2 + ghb, b, msg, false);
#pragma unroll
        for (int c = 0; c < 8; c++) smu[16640 + ghb * 4096 + c * 512 + pm] = msg[c];
    }
    __syncthreads();

    const u64* BmH   = smu + 12288 + gh * 2048;   // [c*256 + m]
    const u64* TmsgH = smu + 16640 + gh * 4096;   // [c*512 + pm]
    const u64* TlogH = smu + 24832 + gh * 512;    // [pm]
    const ulonglong2* A2h = A2 + gh;
    u64* bufAh = smu + gh * 4096;
    u64* bufBh = smu + 8192 + gh * 2048;

    float llx = 0.f, lly = 0.f;
    const u64 ONE2 = pk2f(1.f, 1.f);

    // ---- fused levels 11 (table lookup) -> 10 -> 9 in registers ----
    {
        const int offL  = 128 * 2047 + (t << 11);
        const int off10 = 128 * 1023 + (t << 10);
        const int off9  = 128 * 511  + (t << 9);

        const int4 pL  = *(const int4*)(pos + offL + 4 * nd);
        const int4 xL  = *(const int4*)(x   + offL + 4 * nd);
        const int2 p10 = *(const int2*)(pos + off10 + 2 * nd);
        const int2 x10 = *(const int2*)(x   + off10 + 2 * nd);

        const int pm0 = pL.x * 256 + xL.x, pm1 = pL.y * 256 + xL.y;
        const int pm2 = pL.z * 256 + xL.z, pm3 = pL.w * 256 + xL.w;

        u64 llleaf = add2p(add2p(TlogH[pm0], TlogH[pm1]), add2p(TlogH[pm2], TlogH[pm3]));

        u64 acc9[8];
        u64 nuprodU = ONE2;

#pragma unroll
        for (int s10 = 0; s10 < 2; s10++) {
            const int pma = (s10 == 0) ? pm0 : pm2;
            const int pmb = (s10 == 0) ? pm1 : pm3;
            u64 acc10[8];
#pragma unroll
            for (int c = 0; c < 8; c++)
                acc10[c] = add2p(TmsgH[c * 512 + pma], TmsgH[c * 512 + pmb]);

            int m = (s10 == 0) ? x10.x : x10.y;
            int p = (s10 == 0) ? p10.x : p10.y;
            u64 nu;
#pragma unroll
            for (int c = 0; c < 8; c++) {
                acc10[c] = mul2p(acc10[c], BmH[c * 256 + m]);
                nu = (c == 0) ? acc10[0] : add2p(nu, acc10[c]);
            }
            nuprodU = mul2p(nuprodU, nu);
            float nx, ny; unpk2f(nu, nx, ny);
            u64 r = pk2f(__fdividef(1.f, nx), __fdividef(1.f, ny));
#pragma unroll
            for (int c = 0; c < 8; c++) acc10[c] = mul2p(acc10[c], r);
            matvec8p(A2h + p * 2, acc10, acc9, s10 != 0);
        }
        // level-9 node
        int m = x[off9 + nd];
        int p9 = pos[off9 + nd];
        u64 nu;
#pragma unroll
        for (int c = 0; c < 8; c++) {
            acc9[c] = mul2p(acc9[c], BmH[c * 256 + m]);
            nu = (c == 0) ? acc9[0] : add2p(nu, acc9[c]);
        }
        nuprodU = mul2p(nuprodU, nu);
        float nx, ny; unpk2f(nu, nx, ny);
        u64 r = pk2f(__fdividef(1.f, nx), __fdividef(1.f, ny));
#pragma unroll
        for (int c = 0; c < 8; c++) acc9[c] = mul2p(acc9[c], r);
        u64 msg[8];
        matvec8p(A2h + p9 * 2, acc9, msg, false);
#pragma unroll
        for (int c = 0; c < 8; c++) bufAh[c * 512 + nd] = msg[c];

        float ax, ay, bx, by;
        unpk2f(llleaf, ax, ay);
        unpk2f(nuprodU, bx, by);
        llx += ax + __logf(bx);
        lly += ay + __logf(by);
    }
    __syncthreads();

    // ---- single-phase levels: l = child level (9,8,7) ----
#pragma unroll 1
    for (int l = 9; l >= 7; --l) {
        const int n_pa = 1 << (l - 1);            // 256, 128, 64
        u64* chb = (l & 1) ? bufAh : bufBh;
        const int csh = (l & 1) ? 256 : 128;
        u64* pb  = (l & 1) ? bufBh : bufAh;
        const int ps = (l & 1) ? 256 : 512;
        const int offP = 128 * ((1 << (l - 1)) - 1) + (t << (l - 1));

        if (nd < n_pa) {
            const int pa = nd;
            int m = x[offP + pa];
            int p = pos[offP + pa];
            const ulonglong2* ch2 = (const ulonglong2*)chb;
            u64 v[8];
            u64 nu;
#pragma unroll
            for (int c = 0; c < 8; c++) {
                ulonglong2 pr = ch2[c * csh + pa];
                v[c] = mul2p(add2p(pr.x, pr.y), BmH[c * 256 + m]);
                nu = (c == 0) ? v[0] : add2p(nu, v[c]);
            }
            float nx, ny; unpk2f(nu, nx, ny);
            llx += __logf(nx);
            lly += __logf(ny);
            u64 r = pk2f(__fdividef(1.f, nx), __fdividef(1.f, ny));
#pragma unroll
            for (int c = 0; c < 8; c++) v[c] = mul2p(v[c], r);
            u64 msg[8];
            matvec8p(A2h + p * 2, v, msg, false);
#pragma unroll
            for (int c = 0; c < 8; c++) pb[c * ps + pa] = msg[c];
        }
        __syncthreads();
    }

    // ---- tail: l = 6..1, two independent warps (one per gh) ----
    if (nd < 32) {
        float prodx = 1.f, prody = 1.f;
#pragma unroll 1
        for (int l = 6; l >= 1; --l) {
            const int n_pa = 1 << (l - 1);
            u64* chb = (l & 1) ? bufAh : bufBh;
            const int csh = (l & 1) ? 256 : 128;
            u64* pb  = (l & 1) ? bufBh : bufAh;
            const int ps = (l & 1) ? 256 : 512;
            const int offP = 128 * ((1 << (l - 1)) - 1) + (t << (l - 1));

            if (nd < n_pa) {
                const int pa = nd;
                int m = x[offP + pa];
                const ulonglong2* ch2 = (const ulonglong2*)chb;
                u64 v[8];
                u64 nu;
#pragma unroll
                for (int c = 0; c < 8; c++) {
                    ulonglong2 pr = ch2[c * csh + pa];
                    v[c] = mul2p(add2p(pr.x, pr.y), BmH[c * 256 + m]);
                    nu = (c == 0) ? v[0] : add2p(nu, v[c]);
                }
                float nx, ny; unpk2f(nu, nx, ny);
                prodx *= nx; prody *= ny;
                if (l > 1) {
                    int p = pos[offP + pa];
                    u64 r = pk2f(__fdividef(1.f, nx), __fdividef(1.f, ny));
#pragma unroll
                    for (int c = 0; c < 8; c++) v[c] = mul2p(v[c], r);
                    u64 msg[8];
                    matvec8p(A2h + p * 2, v, msg, false);
#pragma unroll
                    for (int c = 0; c < 8; c++) pb[c * ps + pa] = msg[c];
                }
            }
            __syncwarp();
        }
        llx += __logf(prodx);
        lly += __logf(prody);
    }

    // ---- reduction ----
#pragma unroll
    for (int o = 16; o; o >>= 1) {
        llx += __shfl_xor_sync(0xffffffffu, llx, o);
        lly += __shfl_xor_sync(0xffffffffu, lly, o);
    }
    if ((tid & 31) == 0) {
        atomicAdd(&red[2 * gh + 0], llx);
        atomicAdd(&red[2 * gh + 1], lly);
    }
    __syncthreads();
    if (tid < 4) out[t * 4 + tid] = red[tid];
}

extern "C" void kernel_launch(void* const* d_in, const int* in_sizes, int n_in,
                              void* d_out, int out_size) {
    const float* lA  = (const float*)d_in[0];
    const float* lB  = (const float*)d_in[1];
    const float* lPi = (const float*)d_in[2];
    const float* lSP = (const float*)d_in[3];
    const int*   pos = (const int*)d_in[4];
    const int*   x   = (const int*)d_in[5];
    float*       out = (float*)d_out;

    cudaFuncSetAttribute(htmm_main, cudaFuncAttributeMaxDynamicSharedMemorySize, SMEM_BYTES);

    htmm_main<<<NTREES, NTH, SMEM_BYTES>>>(lA, lB, lPi, lSP, pos, x, out);
}

// round 10
// speedup vs baseline: 2.0518x; 1.0671x over previous
#include <cuda_runtime.h>

#define NTREES 128
#define C 8
#define L 2
#define M 256
#define G 4
#define NTH 1024

typedef unsigned long long u64;

// ---------------- packed f32x2 helpers ----------------
static __device__ __forceinline__ u64 pk2f(float lo, float hi) {
    u64 r; asm("mov.b64 %0,{%1,%2};" : "=l"(r) : "f"(lo), "f"(hi)); return r;
}
static __device__ __forceinline__ void unpk2f(u64 v, float& lo, float& hi) {
    asm("mov.b64 {%0,%1},%2;" : "=f"(lo), "=f"(hi) : "l"(v));
}
static __device__ __forceinline__ u64 fma2p(u64 a, u64 b, u64 c) {
    u64 d; asm("fma.rn.f32x2 %0,%1,%2,%3;" : "=l"(d) : "l"(a), "l"(b), "l"(c)); return d;
}
static __device__ __forceinline__ u64 mul2p(u64 a, u64 b) {
    u64 d; asm("mul.rn.f32x2 %0,%1,%2;" : "=l"(d) : "l"(a), "l"(b)); return d;
}
static __device__ __forceinline__ u64 add2p(u64 a, u64 b) {
    u64 d; asm("add.rn.f32x2 %0,%1,%2;" : "=l"(d) : "l"(a), "l"(b)); return d;
}

// 8x8 matvec: A as ulonglong2 pairs over d; Ap pre-offset by (p*2 + gh).
static __device__ __forceinline__ void matvec8p(const ulonglong2* __restrict__ Ap,
                                                const u64* __restrict__ b,
                                                u64* __restrict__ o, bool acc) {
#pragma unroll
    for (int c = 0; c < 8; c++) {
        u64 mm = acc ? o[c] : 0ull;
#pragma unroll
        for (int d2 = 0; d2 < 4; d2++) {
            ulonglong2 a = Ap[(c * 4 + d2) * 4];
            mm = fma2p(a.x, b[2 * d2], mm);
            mm = fma2p(a.y, b[2 * d2 + 1], mm);
        }
        o[c] = mm;
    }
}

// ---------------- single fused kernel: one CTA per tree ----------------
// smem map (u64 units):
//   bufA [0, 8192)       : [gh][c][512]  (levels 9,7,5,3,1)
//   bufB [8192, 12288)   : [gh][c][256]  (levels 8,6,4,2)
//   BmP  [12288, 16384)  : ull2 [gh][c2][m]   (c-pairs per m -> half the gather loads)
//   A_s  [16384, 16640)  : ulonglong2[c][d2][p][gh]
//   TmsgP[16640, 24832)  : ull2 [gh][c2][pm]  (c-pairs per pm)
//   Tlog [24832, 25856)  : [gh][pm]
//   Pi_s [25856, 25888)  : [p][c][gh]
//   red  [25888, 25890)  : 4 floats
#define SMEM_U64 25890
#define SMEM_BYTES (SMEM_U64 * 8)

__global__ __launch_bounds__(NTH) void htmm_main(const float* __restrict__ lA,
                                                 const float* __restrict__ lB,
                                                 const float* __restrict__ lPi,
                                                 const float* __restrict__ lSP,
                                                 const int* __restrict__ pos,
                                                 const int* __restrict__ x,
                                                 float* __restrict__ out) {
    extern __shared__ u64 smu[];
    float* red = (float*)(smu + 25888);

    const int t = blockIdx.x, tid = threadIdx.x;
    const int gh = tid >> 9, nd = tid & 511;
    const int wid = tid >> 5, lane = tid & 31;

    // ========== per-CTA prologue 1: softmaxes into smem ==========
    // Bm: one warp per (c,g); lane handles 8 m's. Write into paired layout.
    {
        int c = wid >> 2, g = wid & 3;
        float v[8];
        float mx = -1e30f;
#pragma unroll
        for (int j = 0; j < 8; j++) {
            v[j] = lB[(c * M + lane + 32 * j) * G + g];
            mx = fmaxf(mx, v[j]);
        }
#pragma unroll
        for (int o = 16; o; o >>= 1) mx = fmaxf(mx, __shfl_xor_sync(0xffffffffu, mx, o));
        float s = 0.f;
#pragma unroll
        for (int j = 0; j < 8; j++) { v[j] = __expf(v[j] - mx); s += v[j]; }
#pragma unroll
        for (int o = 16; o; o >>= 1) s += __shfl_xor_sync(0xffffffffu, s, o);
        float r = 1.f / s;
        float* BmF = (float*)(smu + 12288);
        int ghw = g >> 1, gl = g & 1, c2 = c >> 1, cl = c & 1;
#pragma unroll
        for (int j = 0; j < 8; j++) {
            int m = lane + 32 * j;
            BmF[(((ghw * 4 + c2) * 256 + m) << 2) + cl * 2 + gl] = v[j] * r;
        }
    }
    // A softmax over c per (d,p,g), fold SP[p,g]  (64 threads)
    if (tid < 64) {
        int d = tid >> 3, p = (tid >> 2) & 1, g = tid & 3;
        float s0 = lSP[0 * G + g], s1 = lSP[1 * G + g];
        float mxs = fmaxf(s0, s1);
        float e0 = __expf(s0 - mxs), e1 = __expf(s1 - mxs);
        float sp = (p == 0 ? e0 : e1) / (e0 + e1);
        float mx = -1e30f;
#pragma unroll
        for (int c = 0; c < C; c++) mx = fmaxf(mx, lA[((c * C + d) * L + p) * G + g]);
        float s = 0.f;
#pragma unroll
        for (int c = 0; c < C; c++) s += __expf(lA[((c * C + d) * L + p) * G + g] - mx);
        float r = sp / s;
        float* AF = (float*)(smu + 16384);
        int d2 = d >> 1, dl = d & 1, ghx = g >> 1, gl = g & 1;
#pragma unroll
        for (int c = 0; c < C; c++) {
            int fi = ((((c * 4 + d2) * 2 + p) * 2 + ghx) * 2 + dl) * 2 + gl;
            AF[fi] = __expf(lA[((c * C + d) * L + p) * G + g] - mx) * r;
        }
    } else if (tid < 72) {
        int t2 = tid - 64;
        int p = t2 >> 2, g = t2 & 3;
        float mx = -1e30f;
#pragma unroll
        for (int c = 0; c < C; c++) mx = fmaxf(mx, lPi[(c * L + p) * G + g]);
        float s = 0.f;
#pragma unroll
        for (int c = 0; c < C; c++) s += __expf(lPi[(c * L + p) * G + g] - mx);
        float r = 1.f / s;
        float* PiF = (float*)(smu + 25856);  // idx p*32 + c*4 + g
#pragma unroll
        for (int c = 0; c < C; c++)
            PiF[p * 32 + c * 4 + g] = __expf(lPi[(c * L + p) * G + g] - mx) * r;
    }
    if (tid < 4) red[tid] = 0.f;
    __syncthreads();

    const ulonglong2* A2 = (const ulonglong2*)(smu + 16384);  // [(c*4+d2)*4 + p*2 + gh]

    // ========== per-CTA prologue 2: leaf table (thread = (pm, gh)) ==========
    {
        const int pm = tid & 511, ghb = tid >> 9;
        const int p = pm >> 8, m = pm & 255;
        const ulonglong2* BmPG = (const ulonglong2*)(smu + 12288) + ghb * 1024;
        u64 b[8], nu;
#pragma unroll
        for (int c2 = 0; c2 < 4; c2++) {
            ulonglong2 bm = BmPG[c2 * 256 + m];
            b[2 * c2]     = mul2p(smu[25856 + p * 16 + (2 * c2) * 2 + ghb], bm.x);
            b[2 * c2 + 1] = mul2p(smu[25856 + p * 16 + (2 * c2 + 1) * 2 + ghb], bm.y);
            u64 pr = add2p(b[2 * c2], b[2 * c2 + 1]);
            nu = (c2 == 0) ? pr : add2p(nu, pr);
        }
        float nx, ny; unpk2f(nu, nx, ny);
        smu[24832 + ghb * 512 + pm] = pk2f(__logf(nx), __logf(ny));
        u64 r = pk2f(__fdividef(1.f, nx), __fdividef(1.f, ny));
#pragma unroll
        for (int c = 0; c < 8; c++) b[c] = mul2p(b[c], r);
        u64 msg[8];
        matvec8p(A2 + p * 2 + ghb, b, msg, false);
        ulonglong2* TP = (ulonglong2*)(smu + 16640) + ghb * 2048;
#pragma unroll
        for (int c2 = 0; c2 < 4; c2++) {
            ulonglong2 w; w.x = msg[2 * c2]; w.y = msg[2 * c2 + 1];
            TP[c2 * 512 + pm] = w;
        }
    }
    __syncthreads();

    const ulonglong2* BmH2  = (const ulonglong2*)(smu + 12288) + gh * 1024; // [c2*256+m]
    const ulonglong2* TmsgH = (const ulonglong2*)(smu + 16640) + gh * 2048; // [c2*512+pm]
    const u64* TlogH = smu + 24832 + gh * 512;
    const ulonglong2* A2h = A2 + gh;
    u64* bufAh = smu + gh * 4096;
    u64* bufBh = smu + 8192 + gh * 2048;

    float llx = 0.f, lly = 0.f;
    const u64 ONE2 = pk2f(1.f, 1.f);

    // ---- fused levels 11 (table lookup) -> 10 -> 9 in registers ----
    {
        const int offL  = 128 * 2047 + (t << 11);
        const int off10 = 128 * 1023 + (t << 10);
        const int off9  = 128 * 511  + (t << 9);

        const int4 pL  = *(const int4*)(pos + offL + 4 * nd);
        const int4 xL  = *(const int4*)(x   + offL + 4 * nd);
        const int2 p10 = *(const int2*)(pos + off10 + 2 * nd);
        const int2 x10 = *(const int2*)(x   + off10 + 2 * nd);

        const int pm0 = pL.x * 256 + xL.x, pm1 = pL.y * 256 + xL.y;
        const int pm2 = pL.z * 256 + xL.z, pm3 = pL.w * 256 + xL.w;

        u64 llleaf = add2p(add2p(TlogH[pm0], TlogH[pm1]), add2p(TlogH[pm2], TlogH[pm3]));

        u64 acc9[8];
        u64 nuprodU = ONE2;

#pragma unroll
        for (int s10 = 0; s10 < 2; s10++) {
            const int pma = (s10 == 0) ? pm0 : pm2;
            const int pmb = (s10 == 0) ? pm1 : pm3;
            int m = (s10 == 0) ? x10.x : x10.y;
            int p = (s10 == 0) ? p10.x : p10.y;

            u64 acc10[8];
            u64 nu;
#pragma unroll
            for (int c2 = 0; c2 < 4; c2++) {
                ulonglong2 ta = TmsgH[c2 * 512 + pma];
                ulonglong2 tb = TmsgH[c2 * 512 + pmb];
                ulonglong2 bm = BmH2[c2 * 256 + m];
                acc10[2 * c2]     = mul2p(add2p(ta.x, tb.x), bm.x);
                acc10[2 * c2 + 1] = mul2p(add2p(ta.y, tb.y), bm.y);
                u64 pr = add2p(acc10[2 * c2], acc10[2 * c2 + 1]);
                nu = (c2 == 0) ? pr : add2p(nu, pr);
            }
            nuprodU = mul2p(nuprodU, nu);
            float nx, ny; unpk2f(nu, nx, ny);
            u64 r = pk2f(__fdividef(1.f, nx), __fdividef(1.f, ny));
#pragma unroll
            for (int c = 0; c < 8; c++) acc10[c] = mul2p(acc10[c], r);
            matvec8p(A2h + p * 2, acc10, acc9, s10 != 0);
        }
        // level-9 node
        int m = x[off9 + nd];
        int p9 = pos[off9 + nd];
        u64 nu;
#pragma unroll
        for (int c2 = 0; c2 < 4; c2++) {
            ulonglong2 bm = BmH2[c2 * 256 + m];
            acc9[2 * c2]     = mul2p(acc9[2 * c2], bm.x);
            acc9[2 * c2 + 1] = mul2p(acc9[2 * c2 + 1], bm.y);
            u64 pr = add2p(acc9[2 * c2], acc9[2 * c2 + 1]);
            nu = (c2 == 0) ? pr : add2p(nu, pr);
        }
        nuprodU = mul2p(nuprodU, nu);
        float nx, ny; unpk2f(nu, nx, ny);
        u64 r = pk2f(__fdividef(1.f, nx), __fdividef(1.f, ny));
#pragma unroll
        for (int c = 0; c < 8; c++) acc9[c] = mul2p(acc9[c], r);
        u64 msg[8];
        matvec8p(A2h + p9 * 2, acc9, msg, false);
#pragma unroll
        for (int c = 0; c < 8; c++) bufAh[c * 512 + nd] = msg[c];

        float ax, ay, bx, by;
        unpk2f(llleaf, ax, ay);
        unpk2f(nuprodU, bx, by);
        llx += ax + __logf(bx);
        lly += ay + __logf(by);
    }
    __syncthreads();

    // ---- single-phase levels: l = child level (9,8,7) ----
#pragma unroll 1
    for (int l = 9; l >= 7; --l) {
        const int n_pa = 1 << (l - 1);            // 256, 128, 64
        u64* chb = (l & 1) ? bufAh : bufBh;
        const int csh = (l & 1) ? 256 : 128;
        u64* pb  = (l & 1) ? bufBh : bufAh;
        const int ps = (l & 1) ? 256 : 512;
        const int offP = 128 * ((1 << (l - 1)) - 1) + (t << (l - 1));

        if (nd < n_pa) {
            const int pa = nd;
            int m = x[offP + pa];
            int p = pos[offP + pa];
            const ulonglong2* ch2 = (const ulonglong2*)chb;
            u64 v[8];
            u64 nu;
#pragma unroll
            for (int c2 = 0; c2 < 4; c2++) {
                ulonglong2 prA = ch2[(2 * c2) * csh + pa];
                ulonglong2 prB = ch2[(2 * c2 + 1) * csh + pa];
                ulonglong2 bm = BmH2[c2 * 256 + m];
                v[2 * c2]     = mul2p(add2p(prA.x, prA.y), bm.x);
                v[2 * c2 + 1] = mul2p(add2p(prB.x, prB.y), bm.y);
                u64 pr = add2p(v[2 * c2], v[2 * c2 + 1]);
                nu = (c2 == 0) ? pr : add2p(nu, pr);
            }
            float nx, ny; unpk2f(nu, nx, ny);
            llx += __logf(nx);
            lly += __logf(ny);
            u64 r = pk2f(__fdividef(1.f, nx), __fdividef(1.f, ny));
#pragma unroll
            for (int c = 0; c < 8; c++) v[c] = mul2p(v[c], r);
            u64 msg[8];
            matvec8p(A2h + p * 2, v, msg, false);
#pragma unroll
            for (int c = 0; c < 8; c++) pb[c * ps + pa] = msg[c];
        }
        __syncthreads();
    }

    // ---- tail: l = 6..1, two independent warps (one per gh) ----
    if (nd < 32) {
        float prodx = 1.f, prody = 1.f;
#pragma unroll 1
        for (int l = 6; l >= 1; --l) {
            const int n_pa = 1 << (l - 1);
            u64* chb = (l & 1) ? bufAh : bufBh;
            const int csh = (l & 1) ? 256 : 128;
            u64* pb  = (l & 1) ? bufBh : bufAh;
            const int ps = (l & 1) ? 256 : 512;
            const int offP = 128 * ((1 << (l - 1)) - 1) + (t << (l - 1));

            if (nd < n_pa) {
                const int pa = nd;
                int m = x[offP + pa];
                const ulonglong2* ch2 = (const ulonglong2*)chb;
                u64 v[8];
                u64 nu;
#pragma unroll
                for (int c2 = 0; c2 < 4; c2++) {
                    ulonglong2 prA = ch2[(2 * c2) * csh + pa];
                    ulonglong2 prB = ch2[(2 * c2 + 1) * csh + pa];
                    ulonglong2 bm = BmH2[c2 * 256 + m];
                    v[2 * c2]     = mul2p(add2p(prA.x, prA.y), bm.x);
                    v[2 * c2 + 1] = mul2p(add2p(prB.x, prB.y), bm.y);
                    u64 pr = add2p(v[2 * c2], v[2 * c2 + 1]);
                    nu = (c2 == 0) ? pr : add2p(nu, pr);
                }
                float nx, ny; unpk2f(nu, nx, ny);
                prodx *= nx; prody *= ny;
                if (l > 1) {
                    int p = pos[offP + pa];
                    u64 r = pk2f(__fdividef(1.f, nx), __fdividef(1.f, ny));
#pragma unroll
                    for (int c = 0; c < 8; c++) v[c] = mul2p(v[c], r);
                    u64 msg[8];
                    matvec8p(A2h + p * 2, v, msg, false);
#pragma unroll
                    for (int c = 0; c < 8; c++) pb[c * ps + pa] = msg[c];
                }
            }
            __syncwarp();
        }
        llx += __logf(prodx);
        lly += __logf(prody);
    }

    // ---- reduction ----
#pragma unroll
    for (int o = 16; o; o >>= 1) {
        llx += __shfl_xor_sync(0xffffffffu, llx, o);
        lly += __shfl_xor_sync(0xffffffffu, lly, o);
    }
    if ((tid & 31) == 0) {
        atomicAdd(&red[2 * gh + 0], llx);
        atomicAdd(&red[2 * gh + 1], lly);
    }
    __syncthreads();
    if (tid < 4) out[t * 4 + tid] = red[tid];
}

extern "C" void kernel_launch(void* const* d_in, const int* in_sizes, int n_in,
                              void* d_out, int out_size) {
    const float* lA  = (const float*)d_in[0];
    const float* lB  = (const float*)d_in[1];
    const float* lPi = (const float*)d_in[2];
    const float* lSP = (const float*)d_in[3];
    const int*   pos = (const int*)d_in[4];
    const int*   x   = (const int*)d_in[5];
    float*       out = (float*)d_out;

    cudaFuncSetAttribute(htmm_main, cudaFuncAttributeMaxDynamicSharedMemorySize, SMEM_BYTES);

    htmm_main<<<NTREES, NTH, SMEM_BYTES>>>(lA, lB, lPi, lSP, pos, x, out);
}